// round 2
// baseline (speedup 1.0000x reference)
#include <cuda_runtime.h>
#include <math.h>

#define NN 100000
#define NE 2000000
#define INC 30
#define HID 40
#define D1 20
#define D2 10
#define NCLS 3
#define NBLK_RED 256

// out layout: logits[3], Y_prob[3], Y_hat[1], A[NN], x3[NN*D1], cell_loss[1]
#define OUT_A 7
#define OUT_X3 (7 + NN)
#define OUT_LOSS (7 + NN + NN * D1)

// ---------------- scratch (device globals; no allocation allowed) ----------------
__device__ __align__(16) float g_h[NN * HID];
__device__ __align__(16) float g_agg[NN * HID];
__device__ __align__(16) float g_x1[NN * HID];
__device__ __align__(16) float g_x3[NN * D1];
__device__ float g_deg[NN];
__device__ float g_dinv[NN];
__device__ float g_a[NN];
__device__ int   g_src[NE];
__device__ int   g_dst[NE];
__device__ float g_norm[NE];
__device__ float g_pmax[NBLK_RED];
__device__ float g_psum[NBLK_RED];
__device__ float g_gmax;
__device__ float g_denom;
__device__ float g_pooled[D1];
__device__ int   g_sel[16];
__device__ int   g_is64;   // 1 if edge_index is int64, 0 if int32

// ---------------- helpers ----------------
__device__ __forceinline__ float selu_f(float x) {
    const float sc = 1.0507009873554805f, al = 1.6732632423543772f;
    return x > 0.f ? sc * x : sc * al * expm1f(x);
}

__device__ __forceinline__ void red_add_v4(float* addr, float a, float b, float c, float d) {
    asm volatile("red.global.add.v4.f32 [%0], {%1,%2,%3,%4};"
                 :: "l"(addr), "f"(a), "f"(b), "f"(c), "f"(d) : "memory");
}

__device__ __forceinline__ int clampn(int v) {
    return v < 0 ? 0 : (v >= NN ? NN - 1 : v);
}

// ---------------- kernels ----------------
// Detect whether edge_index buffer is int64 or int32.
// int64 node ids < 2^31 => every odd 32-bit word is 0. int32 => odd words are
// random node indices (prob of 2048 consecutive zeros ~ 0).
__global__ void k_detect(const int* __restrict__ ei32) {
    __shared__ int any_nz;
    if (threadIdx.x == 0) any_nz = 0;
    __syncthreads();
    int w = ei32[2 * threadIdx.x + 1];
    if (w != 0) atomicOr(&any_nz, 1);
    __syncthreads();
    if (threadIdx.x == 0) g_is64 = any_nz ? 0 : 1;
}

__global__ void k_zero_pre() {
    int i = blockIdx.x * blockDim.x + threadIdx.x;
    if (i < NN) g_deg[i] = 0.f;
    if (i < D1) g_pooled[i] = 0.f;
}

__global__ void k_zero_agg() {
    int i = blockIdx.x * blockDim.x + threadIdx.x;
    if (i < NN * HID) g_agg[i] = 0.f;
}

__global__ void k_prep(const void* __restrict__ eiv, const float* __restrict__ ew) {
    int e = blockIdx.x * blockDim.x + threadIdx.x;
    if (e >= NE) return;
    int s, d;
    if (g_is64) {
        const long long* ei = (const long long*)eiv;
        s = (int)ei[e];
        d = (int)ei[NE + e];
    } else {
        const int* ei = (const int*)eiv;
        s = ei[e];
        d = ei[NE + e];
    }
    s = clampn(s); d = clampn(d);
    g_src[e] = s;
    g_dst[e] = d;
    atomicAdd(&g_deg[d], ew[e]);
}

__global__ void k_dinv() {
    int n = blockIdx.x * blockDim.x + threadIdx.x;
    if (n < NN) g_dinv[n] = rsqrtf(g_deg[n] + 1.0f);
}

__global__ void k_norm(const float* __restrict__ ew) {
    int e = blockIdx.x * blockDim.x + threadIdx.x;
    if (e >= NE) return;
    g_norm[e] = g_dinv[g_src[e]] * ew[e] * g_dinv[g_dst[e]];
}

// h = X @ W  (no bias). xsel==0: X=Xin (external), xsel==1: X=g_x1. Writes g_h.
template <int K, int O>
__global__ void k_mm(const float* __restrict__ Xin, int xsel, const float* __restrict__ W) {
    __shared__ float sW[K * O];
    for (int i = threadIdx.x; i < K * O; i += blockDim.x) sW[i] = W[i];
    __syncthreads();
    int n = blockIdx.x * blockDim.x + threadIdx.x;
    if (n >= NN) return;
    const float* X = (xsel == 0) ? Xin : (const float*)g_x1;
    float acc[O];
#pragma unroll
    for (int o = 0; o < O; o++) acc[o] = 0.f;
    const float* xr = X + (long)n * K;
    for (int k = 0; k < K; k++) {
        float xv = __ldg(xr + k);
#pragma unroll
        for (int o = 0; o < O; o++) acc[o] += xv * sW[k * O + o];
    }
    float* yr = g_h + (long)n * O;
#pragma unroll
    for (int o = 0; o < O; o++) yr[o] = acc[o];
}

// edge scatter: agg[dst] += h[src] * norm  (vector f32x4 reductions)
__global__ void k_agg() {
    int e = blockIdx.x * blockDim.x + threadIdx.x;
    if (e >= NE) return;
    int s = g_src[e], d = g_dst[e];
    float w = g_norm[e];
    const float4* hp = reinterpret_cast<const float4*>(g_h) + s * (HID / 4);
    float* ap = g_agg + d * HID;
#pragma unroll
    for (int j = 0; j < HID / 4; j++) {
        float4 v = __ldg(hp + j);
        red_add_v4(ap + 4 * j, v.x * w, v.y * w, v.z * w, v.w * w);
    }
}

// x1 = selu(layernorm(agg + h*dinv^2 + b))
__global__ void k_post1(const float* __restrict__ b, const float* __restrict__ lw,
                        const float* __restrict__ lb) {
    int n = blockIdx.x * blockDim.x + threadIdx.x;
    if (n >= NN) return;
    float di = g_dinv[n], d2 = di * di;
    float v[HID];
    const float4* ag = reinterpret_cast<const float4*>(g_agg) + n * (HID / 4);
    const float4* hh = reinterpret_cast<const float4*>(g_h) + n * (HID / 4);
    float s = 0.f;
#pragma unroll
    for (int j = 0; j < HID / 4; j++) {
        float4 a4 = ag[j], h4 = hh[j];
        v[4 * j + 0] = a4.x + h4.x * d2 + __ldg(b + 4 * j + 0);
        v[4 * j + 1] = a4.y + h4.y * d2 + __ldg(b + 4 * j + 1);
        v[4 * j + 2] = a4.z + h4.z * d2 + __ldg(b + 4 * j + 2);
        v[4 * j + 3] = a4.w + h4.w * d2 + __ldg(b + 4 * j + 3);
        s += v[4 * j] + v[4 * j + 1] + v[4 * j + 2] + v[4 * j + 3];
    }
    float m = s * (1.f / HID);
    float vs = 0.f;
#pragma unroll
    for (int f = 0; f < HID; f++) { float dd = v[f] - m; vs += dd * dd; }
    float inv = rsqrtf(vs * (1.f / HID) + 1e-5f);
    float* xo = g_x1 + (long)n * HID;
#pragma unroll
    for (int f = 0; f < HID; f++)
        xo[f] = selu_f((v[f] - m) * inv * __ldg(lw + f) + __ldg(lb + f));
}

// x2 = selu(ln(agg + h*dinv^2 + b2)); x3 = selu(x2@Wf+bf) -> g_x3 & out;
// a = tanh(x3@Wt+bt)*sigmoid(x3@Ws+bs) @ Wc + bc
__global__ void k_post2(const float* __restrict__ b2, const float* __restrict__ lw,
                        const float* __restrict__ lb, const float* __restrict__ Wf,
                        const float* __restrict__ bf, const float* __restrict__ Wt,
                        const float* __restrict__ bt, const float* __restrict__ Ws,
                        const float* __restrict__ bs, const float* __restrict__ Wc,
                        const float* __restrict__ bc, float* __restrict__ outx3) {
    __shared__ float sWf[HID * D1];
    __shared__ float sWt[D1 * D2];
    __shared__ float sWs[D1 * D2];
    __shared__ float sWc[D2];
    __shared__ float sbf[D1], sbt[D2], sbs[D2];
    int t = threadIdx.x;
    for (int i = t; i < HID * D1; i += blockDim.x) sWf[i] = Wf[i];
    for (int i = t; i < D1 * D2; i += blockDim.x) { sWt[i] = Wt[i]; sWs[i] = Ws[i]; }
    if (t < D2) { sWc[t] = Wc[t]; sbt[t] = bt[t]; sbs[t] = bs[t]; }
    if (t < D1) sbf[t] = bf[t];
    __syncthreads();
    int n = blockIdx.x * blockDim.x + t;
    if (n >= NN) return;
    float di = g_dinv[n], d2 = di * di;
    float v[HID];
    const float4* ag = reinterpret_cast<const float4*>(g_agg) + n * (HID / 4);
    const float4* hh = reinterpret_cast<const float4*>(g_h) + n * (HID / 4);
    float s = 0.f;
#pragma unroll
    for (int j = 0; j < HID / 4; j++) {
        float4 a4 = ag[j], h4 = hh[j];
        v[4 * j + 0] = a4.x + h4.x * d2 + __ldg(b2 + 4 * j + 0);
        v[4 * j + 1] = a4.y + h4.y * d2 + __ldg(b2 + 4 * j + 1);
        v[4 * j + 2] = a4.z + h4.z * d2 + __ldg(b2 + 4 * j + 2);
        v[4 * j + 3] = a4.w + h4.w * d2 + __ldg(b2 + 4 * j + 3);
        s += v[4 * j] + v[4 * j + 1] + v[4 * j + 2] + v[4 * j + 3];
    }
    float m = s * (1.f / HID);
    float vs = 0.f;
#pragma unroll
    for (int f = 0; f < HID; f++) { float dd = v[f] - m; vs += dd * dd; }
    float inv = rsqrtf(vs * (1.f / HID) + 1e-5f);
#pragma unroll
    for (int f = 0; f < HID; f++)
        v[f] = selu_f((v[f] - m) * inv * __ldg(lw + f) + __ldg(lb + f));
    float x3[D1];
#pragma unroll
    for (int o = 0; o < D1; o++) {
        float acc = sbf[o];
#pragma unroll
        for (int k = 0; k < HID; k++) acc += v[k] * sWf[k * D1 + o];
        x3[o] = selu_f(acc);
    }
    float* xo = g_x3 + (long)n * D1;
    float* xo2 = outx3 + (long)n * D1;
#pragma unroll
    for (int o = 0; o < D1; o++) { xo[o] = x3[o]; xo2[o] = x3[o]; }
    float a = __ldg(bc);
#pragma unroll
    for (int j = 0; j < D2; j++) {
        float zt = sbt[j], zs = sbs[j];
#pragma unroll
        for (int k = 0; k < D1; k++) { zt += x3[k] * sWt[k * D2 + j]; zs += x3[k] * sWs[k * D2 + j]; }
        a += tanhf(zt) * (1.f / (1.f + expf(-zs))) * sWc[j];
    }
    g_a[n] = a;
}

__global__ void k_rmax() {
    __shared__ float sm[256];
    float best = __int_as_float(0xff800000);
    for (int i = blockIdx.x * blockDim.x + threadIdx.x; i < NN; i += gridDim.x * blockDim.x)
        best = fmaxf(best, g_a[i]);
    sm[threadIdx.x] = best; __syncthreads();
    for (int st = 128; st > 0; st >>= 1) {
        if (threadIdx.x < st) sm[threadIdx.x] = fmaxf(sm[threadIdx.x], sm[threadIdx.x + st]);
        __syncthreads();
    }
    if (threadIdx.x == 0) g_pmax[blockIdx.x] = sm[0];
}

__global__ void k_rmax_fin() {
    __shared__ float sm[NBLK_RED];
    sm[threadIdx.x] = g_pmax[threadIdx.x]; __syncthreads();
    for (int st = NBLK_RED / 2; st > 0; st >>= 1) {
        if (threadIdx.x < st) sm[threadIdx.x] = fmaxf(sm[threadIdx.x], sm[threadIdx.x + st]);
        __syncthreads();
    }
    if (threadIdx.x == 0) g_gmax = sm[0];
}

__global__ void k_rsum_pool() {
    __shared__ float sm[256];
    float gm = g_gmax;
    float s = 0.f;
    float acc[D1];
#pragma unroll
    for (int f = 0; f < D1; f++) acc[f] = 0.f;
    for (int i = blockIdx.x * blockDim.x + threadIdx.x; i < NN; i += gridDim.x * blockDim.x) {
        float w = expf(g_a[i] - gm);
        s += w;
        const float4* xr = reinterpret_cast<const float4*>(g_x3) + i * (D1 / 4);
#pragma unroll
        for (int j = 0; j < D1 / 4; j++) {
            float4 t4 = xr[j];
            acc[4 * j + 0] += w * t4.x; acc[4 * j + 1] += w * t4.y;
            acc[4 * j + 2] += w * t4.z; acc[4 * j + 3] += w * t4.w;
        }
    }
    sm[threadIdx.x] = s; __syncthreads();
    for (int st = 128; st > 0; st >>= 1) {
        if (threadIdx.x < st) sm[threadIdx.x] += sm[threadIdx.x + st];
        __syncthreads();
    }
    if (threadIdx.x == 0) g_psum[blockIdx.x] = sm[0];
#pragma unroll
    for (int f = 0; f < D1; f++) {
        float vv = acc[f];
        for (int off = 16; off; off >>= 1) vv += __shfl_down_sync(0xffffffffu, vv, off);
        if ((threadIdx.x & 31) == 0) atomicAdd(&g_pooled[f], vv);
    }
}

__global__ void k_rsum_fin() {
    __shared__ float sm[NBLK_RED];
    sm[threadIdx.x] = g_psum[threadIdx.x]; __syncthreads();
    for (int st = NBLK_RED / 2; st > 0; st >>= 1) {
        if (threadIdx.x < st) sm[threadIdx.x] += sm[threadIdx.x + st];
        __syncthreads();
    }
    if (threadIdx.x == 0) g_denom = sm[0];
}

__global__ void k_writeA(float* __restrict__ outA) {
    int i = blockIdx.x * blockDim.x + threadIdx.x;
    if (i < NN) outA[i] = expf(g_a[i] - g_gmax) / g_denom;
}

// top-8 (argmax passes) then bottom-8 (argmin passes); ties -> lowest index (jax top_k)
__global__ void k_topk() {
    __shared__ float sv[1024];
    __shared__ int si[1024];
    __shared__ int ssel[16];
    int tid = threadIdx.x;
    for (int pass = 0; pass < 16; pass++) {
        bool mx = pass < 8;
        int base = mx ? 0 : 8;
        int cnt = pass - base;
        float best = mx ? __int_as_float(0xff800000) : __int_as_float(0x7f800000);
        int bidx = 0x7fffffff;
        for (int i = tid; i < NN; i += 1024) {
            bool skip = false;
            for (int j = 0; j < cnt; j++)
                if (ssel[base + j] == i) skip = true;
            if (skip) continue;
            float vv = g_a[i];
            bool better = mx ? (vv > best || (vv == best && i < bidx))
                             : (vv < best || (vv == best && i < bidx));
            if (better) { best = vv; bidx = i; }
        }
        sv[tid] = best; si[tid] = bidx; __syncthreads();
        for (int st = 512; st > 0; st >>= 1) {
            if (tid < st) {
                float v2 = sv[tid + st]; int i2 = si[tid + st];
                bool better = mx ? (v2 > sv[tid] || (v2 == sv[tid] && i2 < si[tid]))
                                 : (v2 < sv[tid] || (v2 == sv[tid] && i2 < si[tid]));
                if (better) { sv[tid] = v2; si[tid] = i2; }
            }
            __syncthreads();
        }
        if (tid == 0) { ssel[pass] = si[0]; g_sel[pass] = si[0]; }
        __syncthreads();
    }
}

__global__ void k_final(const float* __restrict__ Wcls, const float* __restrict__ bcls,
                        const float* __restrict__ Wcell, const float* __restrict__ bcell,
                        const int* __restrict__ labelp, float* __restrict__ out) {
    if (threadIdx.x != 0) return;
    float denom = g_denom;
    float pooled[D1];
#pragma unroll
    for (int f = 0; f < D1; f++) pooled[f] = g_pooled[f] / denom;
    float logits[NCLS];
#pragma unroll
    for (int c = 0; c < NCLS; c++) {
        float s = bcls[c];
#pragma unroll
        for (int f = 0; f < D1; f++) s += pooled[f] * Wcls[f * NCLS + c];
        logits[c] = s;
    }
    float mx = fmaxf(logits[0], fmaxf(logits[1], logits[2]));
    float e0 = expf(logits[0] - mx), e1 = expf(logits[1] - mx), e2 = expf(logits[2] - mx);
    float es = e0 + e1 + e2;
    int yhat = 0;
    if (logits[1] > logits[yhat]) yhat = 1;
    if (logits[2] > logits[yhat]) yhat = 2;
    out[0] = logits[0]; out[1] = logits[1]; out[2] = logits[2];
    out[3] = e0 / es; out[4] = e1 / es; out[5] = e2 / es;
    out[6] = (float)yhat;
    int label = labelp[0];
    if (label < 0) label = 0;
    if (label >= NCLS) label = NCLS - 1;
    const float* Wl = Wcell + label * D1 * 2;
    const float* bl = bcell + label * 2;
    float loss = 0.f;
    for (int i = 0; i < 16; i++) {
        int node = g_sel[i];
        if (node < 0 || node >= NN) node = 0;
        int tgt = (i < 8) ? 1 : 0;
        const float* xr = g_x3 + (long)node * D1;
        float l0 = bl[0], l1 = bl[1];
#pragma unroll
        for (int f = 0; f < D1; f++) { l0 += xr[f] * Wl[f * 2]; l1 += xr[f] * Wl[f * 2 + 1]; }
        float u0 = l0 + (tgt == 1 ? 1.f : 0.f);
        float u1 = l1 + (tgt == 0 ? 1.f : 0.f);
        float mm = fmaxf(u0, u1);
        float lse = mm + logf(expf(u0 - mm) + expf(u1 - mm));
        float sy = tgt ? l1 : l0;
        loss += lse - sy;
    }
    out[OUT_LOSS] = loss * (1.f / 16.f);
}

// ---------------- launch ----------------
extern "C" void kernel_launch(void* const* d_in, const int* in_sizes, int n_in,
                              void* d_out, int out_size) {
    const float* x = (const float*)d_in[0];
    const void* ei = d_in[1];
    const float* ew = (const float*)d_in[2];
    const int* label = (const int*)d_in[3];
    const float* W1 = (const float*)d_in[4];
    const float* b1 = (const float*)d_in[5];
    const float* ln1w = (const float*)d_in[6];
    const float* ln1b = (const float*)d_in[7];
    const float* W2 = (const float*)d_in[8];
    const float* b2 = (const float*)d_in[9];
    const float* ln2w = (const float*)d_in[10];
    const float* ln2b = (const float*)d_in[11];
    const float* Wf = (const float*)d_in[12];
    const float* bf = (const float*)d_in[13];
    const float* Wt = (const float*)d_in[14];
    const float* bt = (const float*)d_in[15];
    const float* Ws = (const float*)d_in[16];
    const float* bs = (const float*)d_in[17];
    const float* Wc = (const float*)d_in[18];
    const float* bc = (const float*)d_in[19];
    const float* Wcls = (const float*)d_in[20];
    const float* bcls = (const float*)d_in[21];
    const float* Wcell = (const float*)d_in[22];
    const float* bcell = (const float*)d_in[23];
    float* out = (float*)d_out;

    int nb_node128 = (NN + 127) / 128;
    int nb_node256 = (NN + 255) / 256;
    int nb_edge = (NE + 255) / 256;
    int nb_aggz = (NN * HID + 255) / 256;

    k_detect<<<1, 1024>>>((const int*)ei);
    k_zero_pre<<<nb_node256, 256>>>();
    k_prep<<<nb_edge, 256>>>(ei, ew);
    k_dinv<<<nb_node256, 256>>>();
    k_norm<<<nb_edge, 256>>>(ew);

    // layer 1
    k_mm<INC, HID><<<nb_node128, 128>>>(x, 0, W1);
    k_zero_agg<<<nb_aggz, 256>>>();
    k_agg<<<nb_edge, 256>>>();
    k_post1<<<nb_node128, 128>>>(b1, ln1w, ln1b);

    // layer 2
    k_mm<HID, HID><<<nb_node128, 128>>>(x, 1, W2);
    k_zero_agg<<<nb_aggz, 256>>>();
    k_agg<<<nb_edge, 256>>>();
    k_post2<<<nb_node128, 128>>>(b2, ln2w, ln2b, Wf, bf, Wt, bt, Ws, bs, Wc, bc,
                                 out + OUT_X3);

    // softmax + pooled
    k_rmax<<<NBLK_RED, 256>>>();
    k_rmax_fin<<<1, NBLK_RED>>>();
    k_rsum_pool<<<NBLK_RED, 256>>>();
    k_rsum_fin<<<1, NBLK_RED>>>();
    k_writeA<<<nb_node256, 256>>>(out + OUT_A);

    // top/bottom-k + tail
    k_topk<<<1, 1024>>>();
    k_final<<<1, 32>>>(Wcls, bcls, Wcell, bcell, label, out);
}

// round 3
// speedup vs baseline: 2.9434x; 2.9434x over previous
#include <cuda_runtime.h>
#include <math.h>

#define NN 100000
#define NE 2000000
#define INC 30
#define HID 40
#define D1 20
#define D2 10
#define NCLS 3
#define NB_SP 128   // softpool blocks
#define NB_TK 128   // topk stage-1 blocks

// out layout: logits[3], Y_prob[3], Y_hat[1], A[NN], x3[NN*D1], cell_loss[1]
#define OUT_A 7
#define OUT_X3 (7 + NN)
#define OUT_LOSS (7 + NN + NN * D1)

// ---------------- scratch ----------------
__device__ __align__(16) float g_h[NN * HID];
__device__ __align__(16) float g_agg[NN * HID];
__device__ __align__(16) float g_x3[NN * D1];
__device__ float g_a[NN];
__device__ float g_deg[NN];
__device__ float g_dinv[NN];
__device__ int   g_cnt[NN];
__device__ int   g_pref[NN];
__device__ int   g_bsum[128];
__device__ int   g_bpref[128];
__device__ int   g_rowstart[NN + 1];
__device__ int   g_cur[NN];
__device__ int2  g_sd[NE];
__device__ unsigned long long g_csr[NE];
__device__ float g_bm[NB_SP];
__device__ float g_bs[NB_SP];
__device__ float g_bp[NB_SP * D1];
__device__ float g_gmax;
__device__ float g_denom;
__device__ float g_pooled[D1];
__device__ float g_cand_v[2 * NB_TK * 8];
__device__ int   g_cand_i[2 * NB_TK * 8];
__device__ int   g_is64;

// ---------------- helpers ----------------
__device__ __forceinline__ float selu_f(float x) {
    const float sc = 1.0507009873554805f, al = 1.6732632423543772f;
    return x > 0.f ? sc * x : sc * al * expm1f(x);
}
__device__ __forceinline__ int clampn(int v) {
    return v < 0 ? 0 : (v >= NN ? NN - 1 : v);
}

// ---------------- kernels ----------------
__global__ void k_detect(const int* __restrict__ ei32) {
    __shared__ int any_nz;
    if (threadIdx.x == 0) any_nz = 0;
    __syncthreads();
    if (ei32[2 * threadIdx.x + 1] != 0) atomicOr(&any_nz, 1);
    __syncthreads();
    if (threadIdx.x == 0) g_is64 = any_nz ? 0 : 1;
}

__global__ void k_zero() {
    int i = blockIdx.x * blockDim.x + threadIdx.x;
    if (i < NN) { g_deg[i] = 0.f; g_cnt[i] = 0; }
}

__global__ void k_prep(const void* __restrict__ eiv, const float* __restrict__ ew) {
    int e = blockIdx.x * blockDim.x + threadIdx.x;
    if (e >= NE) return;
    int s, d;
    if (g_is64) {
        const long long* ei = (const long long*)eiv;
        s = (int)ei[e]; d = (int)ei[NE + e];
    } else {
        const int* ei = (const int*)eiv;
        s = ei[e]; d = ei[NE + e];
    }
    s = clampn(s); d = clampn(d);
    g_sd[e] = make_int2(s, d);
    atomicAdd(&g_deg[d], ew[e]);
    atomicAdd(&g_cnt[d], 1);
}

// block-local exclusive scan of g_cnt
__global__ void k_scan1() {
    __shared__ int sm[1024];
    int t = threadIdx.x;
    int gid = blockIdx.x * 1024 + t;
    int x = (gid < NN) ? g_cnt[gid] : 0;
    sm[t] = x; __syncthreads();
    for (int off = 1; off < 1024; off <<= 1) {
        int v = (t >= off) ? sm[t - off] : 0;
        __syncthreads();
        sm[t] += v;
        __syncthreads();
    }
    if (gid < NN) g_pref[gid] = sm[t] - x;
    if (t == 1023) g_bsum[blockIdx.x] = sm[1023];
}

__global__ void k_scan2(int nblk) {
    __shared__ int sm[128];
    int t = threadIdx.x;
    int x = (t < nblk) ? g_bsum[t] : 0;
    sm[t] = x; __syncthreads();
    for (int off = 1; off < 128; off <<= 1) {
        int v = (t >= off) ? sm[t - off] : 0;
        __syncthreads();
        sm[t] += v;
        __syncthreads();
    }
    if (t < nblk) g_bpref[t] = sm[t] - x;
}

__global__ void k_scan3() {
    int gid = blockIdx.x * 1024 + threadIdx.x;
    if (gid < NN) {
        int rs = g_pref[gid] + g_bpref[blockIdx.x];
        g_rowstart[gid] = rs;
        g_cur[gid] = rs;
        g_dinv[gid] = rsqrtf(g_deg[gid] + 1.0f);
    }
    if (gid == 0) g_rowstart[NN] = NE;
}

// h = x @ W1
__global__ void k_mm1(const float* __restrict__ X, const float* __restrict__ W) {
    __shared__ float sW[INC * HID];
    for (int i = threadIdx.x; i < INC * HID; i += blockDim.x) sW[i] = W[i];
    __syncthreads();
    int n = blockIdx.x * blockDim.x + threadIdx.x;
    if (n >= NN) return;
    float acc[HID];
#pragma unroll
    for (int o = 0; o < HID; o++) acc[o] = 0.f;
    const float* xr = X + (long)n * INC;
#pragma unroll
    for (int k = 0; k < INC; k++) {
        float xv = __ldg(xr + k);
#pragma unroll
        for (int o = 0; o < HID; o++) acc[o] += xv * sW[k * HID + o];
    }
    float* yr = g_h + (long)n * HID;
#pragma unroll
    for (int o = 0; o < HID; o++) yr[o] = acc[o];
}

// build CSR entries (src, norm) packed 8B
__global__ void k_scatter(const float* __restrict__ ew) {
    int e = blockIdx.x * blockDim.x + threadIdx.x;
    if (e >= NE) return;
    int2 sd = g_sd[e];
    float w = g_dinv[sd.x] * ew[e] * g_dinv[sd.y];
    int pos = atomicAdd(&g_cur[sd.y], 1);
    unsigned long long ent = ((unsigned long long)__float_as_uint(w) << 32) |
                             (unsigned int)sd.x;
    g_csr[pos] = ent;
}

// CSR aggregation: warp per node, lanes 0-9 own float4 chunks.
// agg[n] = sum_e w_e * h[src_e] + h[n]*dinv[n]^2 + b
__global__ void k_aggc(const float* __restrict__ b) {
    int warp = blockIdx.x * 8 + (threadIdx.x >> 5);
    if (warp >= NN) return;
    int lane = threadIdx.x & 31;
    int beg = g_rowstart[warp], end = g_rowstart[warp + 1];
    const float4* h4 = reinterpret_cast<const float4*>(g_h);
    float4 acc = make_float4(0.f, 0.f, 0.f, 0.f);
    int e = beg;
    for (; e + 1 < end; e += 2) {
        unsigned long long e0 = g_csr[e];
        unsigned long long e1 = g_csr[e + 1];
        int s0 = (int)(unsigned int)e0;
        int s1 = (int)(unsigned int)e1;
        float w0 = __uint_as_float((unsigned int)(e0 >> 32));
        float w1 = __uint_as_float((unsigned int)(e1 >> 32));
        if (lane < 10) {
            float4 v0 = __ldg(h4 + s0 * 10 + lane);
            float4 v1 = __ldg(h4 + s1 * 10 + lane);
            acc.x += v0.x * w0 + v1.x * w1;
            acc.y += v0.y * w0 + v1.y * w1;
            acc.z += v0.z * w0 + v1.z * w1;
            acc.w += v0.w * w0 + v1.w * w1;
        }
    }
    if (e < end) {
        unsigned long long e0 = g_csr[e];
        int s0 = (int)(unsigned int)e0;
        float w0 = __uint_as_float((unsigned int)(e0 >> 32));
        if (lane < 10) {
            float4 v0 = __ldg(h4 + s0 * 10 + lane);
            acc.x += v0.x * w0; acc.y += v0.y * w0;
            acc.z += v0.z * w0; acc.w += v0.w * w0;
        }
    }
    if (lane < 10) {
        float di = g_dinv[warp], d2 = di * di;
        float4 hv = h4[warp * 10 + lane];
        float4 bv = __ldg(reinterpret_cast<const float4*>(b) + lane);
        float4 r;
        r.x = acc.x + hv.x * d2 + bv.x;
        r.y = acc.y + hv.y * d2 + bv.y;
        r.z = acc.z + hv.z * d2 + bv.z;
        r.w = acc.w + hv.w * d2 + bv.w;
        reinterpret_cast<float4*>(g_agg)[warp * 10 + lane] = r;
    }
}

// x1 = selu(ln(agg)); h2 = x1 @ W2 -> g_h (overwrite)
__global__ void k_post1mm(const float* __restrict__ lw, const float* __restrict__ lb,
                          const float* __restrict__ W2) {
    __shared__ float sW[HID * HID];
    for (int i = threadIdx.x; i < HID * HID; i += blockDim.x) sW[i] = W2[i];
    __syncthreads();
    int n = blockIdx.x * blockDim.x + threadIdx.x;
    if (n >= NN) return;
    float v[HID];
    const float4* ag = reinterpret_cast<const float4*>(g_agg) + n * (HID / 4);
    float s = 0.f;
#pragma unroll
    for (int j = 0; j < HID / 4; j++) {
        float4 a4 = ag[j];
        v[4 * j + 0] = a4.x; v[4 * j + 1] = a4.y;
        v[4 * j + 2] = a4.z; v[4 * j + 3] = a4.w;
        s += a4.x + a4.y + a4.z + a4.w;
    }
    float m = s * (1.f / HID);
    float vs = 0.f;
#pragma unroll
    for (int f = 0; f < HID; f++) { float dd = v[f] - m; vs += dd * dd; }
    float inv = rsqrtf(vs * (1.f / HID) + 1e-5f);
#pragma unroll
    for (int f = 0; f < HID; f++)
        v[f] = selu_f((v[f] - m) * inv * __ldg(lw + f) + __ldg(lb + f));
    float acc[HID];
#pragma unroll
    for (int o = 0; o < HID; o++) acc[o] = 0.f;
#pragma unroll
    for (int k = 0; k < HID; k++) {
        float xv = v[k];
#pragma unroll
        for (int o = 0; o < HID; o++) acc[o] += xv * sW[k * HID + o];
    }
    float* yr = g_h + (long)n * HID;
#pragma unroll
    for (int o = 0; o < HID; o++) yr[o] = acc[o];
}

// x2 = selu(ln(agg)); x3 = selu(x2@Wf+bf); a = gated attention score
__global__ void k_post2(const float* __restrict__ lw, const float* __restrict__ lb,
                        const float* __restrict__ Wf, const float* __restrict__ bf,
                        const float* __restrict__ Wt, const float* __restrict__ bt,
                        const float* __restrict__ Ws, const float* __restrict__ bs,
                        const float* __restrict__ Wc, const float* __restrict__ bc,
                        float* __restrict__ outx3) {
    __shared__ float sWf[HID * D1];
    __shared__ float sWt[D1 * D2];
    __shared__ float sWs[D1 * D2];
    __shared__ float sWc[D2];
    __shared__ float sbf[D1], sbt[D2], sbs[D2];
    int t = threadIdx.x;
    for (int i = t; i < HID * D1; i += blockDim.x) sWf[i] = Wf[i];
    for (int i = t; i < D1 * D2; i += blockDim.x) { sWt[i] = Wt[i]; sWs[i] = Ws[i]; }
    if (t < D2) { sWc[t] = Wc[t]; sbt[t] = bt[t]; sbs[t] = bs[t]; }
    if (t < D1) sbf[t] = bf[t];
    __syncthreads();
    int n = blockIdx.x * blockDim.x + t;
    if (n >= NN) return;
    float v[HID];
    const float4* ag = reinterpret_cast<const float4*>(g_agg) + n * (HID / 4);
    float s = 0.f;
#pragma unroll
    for (int j = 0; j < HID / 4; j++) {
        float4 a4 = ag[j];
        v[4 * j + 0] = a4.x; v[4 * j + 1] = a4.y;
        v[4 * j + 2] = a4.z; v[4 * j + 3] = a4.w;
        s += a4.x + a4.y + a4.z + a4.w;
    }
    float m = s * (1.f / HID);
    float vs = 0.f;
#pragma unroll
    for (int f = 0; f < HID; f++) { float dd = v[f] - m; vs += dd * dd; }
    float inv = rsqrtf(vs * (1.f / HID) + 1e-5f);
#pragma unroll
    for (int f = 0; f < HID; f++)
        v[f] = selu_f((v[f] - m) * inv * __ldg(lw + f) + __ldg(lb + f));
    float x3[D1];
#pragma unroll
    for (int o = 0; o < D1; o++) {
        float acc = sbf[o];
#pragma unroll
        for (int k = 0; k < HID; k++) acc += v[k] * sWf[k * D1 + o];
        x3[o] = selu_f(acc);
    }
    float* xo = g_x3 + (long)n * D1;
    float* xo2 = outx3 + (long)n * D1;
#pragma unroll
    for (int o = 0; o < D1; o++) { xo[o] = x3[o]; xo2[o] = x3[o]; }
    float a = __ldg(bc);
#pragma unroll
    for (int j = 0; j < D2; j++) {
        float zt = sbt[j], zs = sbs[j];
#pragma unroll
        for (int k = 0; k < D1; k++) { zt += x3[k] * sWt[k * D2 + j]; zs += x3[k] * sWs[k * D2 + j]; }
        a += tanhf(zt) * (1.f / (1.f + expf(-zs))) * sWc[j];
    }
    g_a[n] = a;
}

// per-block: m_b = max(a), s_b = sum exp(a-m_b), p_b = sum exp(a-m_b)*x3
__global__ void k_softpool() {
    __shared__ float sm[256];
    __shared__ float sbp[D1];
    int t = threadIdx.x;
    // pass 1: block max
    float mx = __int_as_float(0xff800000);
    for (int i = blockIdx.x * 256 + t; i < NN; i += NB_SP * 256)
        mx = fmaxf(mx, g_a[i]);
    sm[t] = mx; __syncthreads();
    for (int st = 128; st > 0; st >>= 1) {
        if (t < st) sm[t] = fmaxf(sm[t], sm[t + st]);
        __syncthreads();
    }
    float mb = sm[0];
    __syncthreads();
    // pass 2: sums
    float ssum = 0.f;
    float acc[D1];
#pragma unroll
    for (int f = 0; f < D1; f++) acc[f] = 0.f;
    for (int i = blockIdx.x * 256 + t; i < NN; i += NB_SP * 256) {
        float w = expf(g_a[i] - mb);
        ssum += w;
        const float4* xr = reinterpret_cast<const float4*>(g_x3) + i * (D1 / 4);
#pragma unroll
        for (int j = 0; j < D1 / 4; j++) {
            float4 t4 = xr[j];
            acc[4 * j + 0] += w * t4.x; acc[4 * j + 1] += w * t4.y;
            acc[4 * j + 2] += w * t4.z; acc[4 * j + 3] += w * t4.w;
        }
    }
    sm[t] = ssum; __syncthreads();
    for (int st = 128; st > 0; st >>= 1) {
        if (t < st) sm[t] += sm[t + st];
        __syncthreads();
    }
    if (t == 0) { g_bm[blockIdx.x] = mb; g_bs[blockIdx.x] = sm[0]; }
    if (t < D1) sbp[t] = 0.f;
    __syncthreads();
#pragma unroll
    for (int f = 0; f < D1; f++) {
        float vv = acc[f];
        for (int off = 16; off; off >>= 1) vv += __shfl_down_sync(0xffffffffu, vv, off);
        if ((t & 31) == 0) atomicAdd(&sbp[f], vv);
    }
    __syncthreads();
    if (t < D1) g_bp[blockIdx.x * D1 + t] = sbp[t];
}

__global__ void k_spfin() {
    __shared__ float sm[128];
    int t = threadIdx.x;
    float mt = g_bm[t];
    sm[t] = mt; __syncthreads();
    for (int st = 64; st > 0; st >>= 1) {
        if (t < st) sm[t] = fmaxf(sm[t], sm[t + st]);
        __syncthreads();
    }
    float M = sm[0];
    __syncthreads();
    float scale = expf(mt - M);
    sm[t] = g_bs[t] * scale; __syncthreads();
    for (int st = 64; st > 0; st >>= 1) {
        if (t < st) sm[t] += sm[t + st];
        __syncthreads();
    }
    float denom = sm[0];
    if (t == 0) { g_gmax = M; g_denom = denom; }
    __syncthreads();
    for (int f = 0; f < D1; f++) {
        sm[t] = g_bp[t * D1 + f] * scale;
        __syncthreads();
        for (int st = 64; st > 0; st >>= 1) {
            if (t < st) sm[t] += sm[t + st];
            __syncthreads();
        }
        if (t == 0) g_pooled[f] = sm[0] / denom;
        __syncthreads();
    }
}

// stage-1 topk: each block = 1024 contiguous elements, 1/thread.
// also writes A (softmax) output.
__global__ void k_topk1(float* __restrict__ outA) {
    __shared__ float sv[1024];
    __shared__ int si[1024];
    int t = threadIdx.x;
    int gid = blockIdx.x * 1024 + t;
    bool valid = gid < NN;
    float a = valid ? g_a[gid] : 0.f;
    if (valid) outA[gid] = expf(a - g_gmax) / g_denom;
    float vt = valid ? a : __int_as_float(0xff800000);
    float vb = valid ? a : __int_as_float(0x7f800000);
    int myi = valid ? gid : 0x7fffffff;
    // top-8
    for (int pass = 0; pass < 8; pass++) {
        sv[t] = vt; si[t] = myi; __syncthreads();
        for (int st = 512; st > 0; st >>= 1) {
            if (t < st) {
                float v2 = sv[t + st]; int i2 = si[t + st];
                if (v2 > sv[t] || (v2 == sv[t] && i2 < si[t])) { sv[t] = v2; si[t] = i2; }
            }
            __syncthreads();
        }
        if (t == 0) {
            g_cand_v[blockIdx.x * 8 + pass] = sv[0];
            g_cand_i[blockIdx.x * 8 + pass] = si[0];
        }
        if (myi == si[0]) vt = __int_as_float(0xff800000);
        __syncthreads();
    }
    // bottom-8
    for (int pass = 0; pass < 8; pass++) {
        sv[t] = vb; si[t] = myi; __syncthreads();
        for (int st = 512; st > 0; st >>= 1) {
            if (t < st) {
                float v2 = sv[t + st]; int i2 = si[t + st];
                if (v2 < sv[t] || (v2 == sv[t] && i2 < si[t])) { sv[t] = v2; si[t] = i2; }
            }
            __syncthreads();
        }
        if (t == 0) {
            g_cand_v[NB_TK * 8 + blockIdx.x * 8 + pass] = sv[0];
            g_cand_i[NB_TK * 8 + blockIdx.x * 8 + pass] = si[0];
        }
        if (myi == si[0]) vb = __int_as_float(0x7f800000);
        __syncthreads();
    }
}

// stage-2 merge (1024 top candidates, 1024 bottom candidates) + final tail math
__global__ void k_topk2(const float* __restrict__ Wcls, const float* __restrict__ bcls,
                        const float* __restrict__ Wcell, const float* __restrict__ bcell,
                        const int* __restrict__ labelp, float* __restrict__ out) {
    __shared__ float sv[1024];
    __shared__ int si[1024];
    __shared__ int ssel[16];
    int t = threadIdx.x;
    float vt = g_cand_v[t];
    int it = g_cand_i[t];
    for (int pass = 0; pass < 8; pass++) {
        sv[t] = vt; si[t] = it; __syncthreads();
        for (int st = 512; st > 0; st >>= 1) {
            if (t < st) {
                float v2 = sv[t + st]; int i2 = si[t + st];
                if (v2 > sv[t] || (v2 == sv[t] && i2 < si[t])) { sv[t] = v2; si[t] = i2; }
            }
            __syncthreads();
        }
        if (t == 0) ssel[pass] = si[0];
        if (it == si[0]) vt = __int_as_float(0xff800000);
        __syncthreads();
    }
    float vb = g_cand_v[NB_TK * 8 + t];
    int ib = g_cand_i[NB_TK * 8 + t];
    for (int pass = 0; pass < 8; pass++) {
        sv[t] = vb; si[t] = ib; __syncthreads();
        for (int st = 512; st > 0; st >>= 1) {
            if (t < st) {
                float v2 = sv[t + st]; int i2 = si[t + st];
                if (v2 < sv[t] || (v2 == sv[t] && i2 < si[t])) { sv[t] = v2; si[t] = i2; }
            }
            __syncthreads();
        }
        if (t == 0) ssel[8 + pass] = si[0];
        if (ib == si[0]) vb = __int_as_float(0x7f800000);
        __syncthreads();
    }
    if (t != 0) return;
    // bag logits + softmax + argmax
    float logits[NCLS];
#pragma unroll
    for (int c = 0; c < NCLS; c++) {
        float s = bcls[c];
#pragma unroll
        for (int f = 0; f < D1; f++) s += g_pooled[f] * Wcls[f * NCLS + c];
        logits[c] = s;
    }
    float mx = fmaxf(logits[0], fmaxf(logits[1], logits[2]));
    float e0 = expf(logits[0] - mx), e1 = expf(logits[1] - mx), e2 = expf(logits[2] - mx);
    float es = e0 + e1 + e2;
    int yhat = 0;
    if (logits[1] > logits[yhat]) yhat = 1;
    if (logits[2] > logits[yhat]) yhat = 2;
    out[0] = logits[0]; out[1] = logits[1]; out[2] = logits[2];
    out[3] = e0 / es; out[4] = e1 / es; out[5] = e2 / es;
    out[6] = (float)yhat;
    // cell loss
    int label = labelp[0];
    if (label < 0) label = 0;
    if (label >= NCLS) label = NCLS - 1;
    const float* Wl = Wcell + label * D1 * 2;
    const float* bl = bcell + label * 2;
    float loss = 0.f;
    for (int i = 0; i < 16; i++) {
        int node = ssel[i];
        if (node < 0 || node >= NN) node = 0;
        int tgt = (i < 8) ? 1 : 0;
        const float* xr = g_x3 + (long)node * D1;
        float l0 = bl[0], l1 = bl[1];
#pragma unroll
        for (int f = 0; f < D1; f++) { l0 += xr[f] * Wl[f * 2]; l1 += xr[f] * Wl[f * 2 + 1]; }
        float u0 = l0 + (tgt == 1 ? 1.f : 0.f);
        float u1 = l1 + (tgt == 0 ? 1.f : 0.f);
        float mm = fmaxf(u0, u1);
        float lse = mm + logf(expf(u0 - mm) + expf(u1 - mm));
        float sy = tgt ? l1 : l0;
        loss += lse - sy;
    }
    out[OUT_LOSS] = loss * (1.f / 16.f);
}

// ---------------- launch ----------------
extern "C" void kernel_launch(void* const* d_in, const int* in_sizes, int n_in,
                              void* d_out, int out_size) {
    const float* x = (const float*)d_in[0];
    const void* ei = d_in[1];
    const float* ew = (const float*)d_in[2];
    const int* label = (const int*)d_in[3];
    const float* W1 = (const float*)d_in[4];
    const float* b1 = (const float*)d_in[5];
    const float* ln1w = (const float*)d_in[6];
    const float* ln1b = (const float*)d_in[7];
    const float* W2 = (const float*)d_in[8];
    const float* b2 = (const float*)d_in[9];
    const float* ln2w = (const float*)d_in[10];
    const float* ln2b = (const float*)d_in[11];
    const float* Wf = (const float*)d_in[12];
    const float* bf = (const float*)d_in[13];
    const float* Wt = (const float*)d_in[14];
    const float* bt = (const float*)d_in[15];
    const float* Ws = (const float*)d_in[16];
    const float* bs = (const float*)d_in[17];
    const float* Wc = (const float*)d_in[18];
    const float* bc = (const float*)d_in[19];
    const float* Wcls = (const float*)d_in[20];
    const float* bcls = (const float*)d_in[21];
    const float* Wcell = (const float*)d_in[22];
    const float* bcell = (const float*)d_in[23];
    float* out = (float*)d_out;

    int nb_scan = (NN + 1023) / 1024;        // 98
    int nb_edge = (NE + 255) / 256;          // 7813
    int nb_node = (NN + 127) / 128;          // 782
    int nb_aggc = (NN + 7) / 8;              // 12500

    k_detect<<<1, 1024>>>((const int*)ei);
    k_zero<<<nb_scan, 1024>>>();
    k_prep<<<nb_edge, 256>>>(ei, ew);
    k_scan1<<<nb_scan, 1024>>>();
    k_scan2<<<1, 128>>>(nb_scan);
    k_scan3<<<nb_scan, 1024>>>();
    k_mm1<<<nb_node, 128>>>(x, W1);
    k_scatter<<<nb_edge, 256>>>(ew);

    // layer 1
    k_aggc<<<nb_aggc, 256>>>(b1);
    k_post1mm<<<nb_node, 128>>>(ln1w, ln1b, W2);
    // layer 2
    k_aggc<<<nb_aggc, 256>>>(b2);
    k_post2<<<nb_node, 128>>>(ln2w, ln2b, Wf, bf, Wt, bt, Ws, bs, Wc, bc,
                              out + OUT_X3);

    // softmax + pool
    k_softpool<<<NB_SP, 256>>>();
    k_spfin<<<1, 128>>>();

    // topk (+A write) and tail (+final)
    k_topk1<<<NB_TK, 1024>>>(out + OUT_A);
    k_topk2<<<1, 1024>>>(Wcls, bcls, Wcell, bcell, label, out);
}

// round 5
// speedup vs baseline: 3.3411x; 1.1351x over previous
#include <cuda_runtime.h>
#include <math.h>

#define NN 100000
#define NE 2000000
#define INC 30
#define HID 40
#define D1 20
#define D2 10
#define NCLS 3
#define NB_SP 128   // softpool blocks
#define NB_TK 128   // topk stage-1 blocks

// out layout: logits[3], Y_prob[3], Y_hat[1], A[NN], x3[NN*D1], cell_loss[1]
#define OUT_A 7
#define OUT_X3 (7 + NN)
#define OUT_LOSS (7 + NN + NN * D1)

// ---------------- scratch ----------------
__device__ __align__(16) float g_h[NN * HID];
__device__ __align__(16) float g_agg[NN * HID];
__device__ __align__(16) float g_x3[NN * D1];
__device__ float g_a[NN];
__device__ float g_deg[NN];
__device__ float g_dinv[NN];
__device__ int   g_cnt[NN];
__device__ int   g_pref[NN];
__device__ int   g_bsum[128];
__device__ int   g_rowstart[NN + 1];
__device__ int   g_cur[NN];
__device__ int2  g_sd[NE];
__device__ unsigned long long g_csr[NE];
__device__ float g_bm[NB_SP];
__device__ float g_bs[NB_SP];
__device__ float g_bp[NB_SP * D1];
__device__ float g_gmax;
__device__ float g_denom;
__device__ float g_pooled[D1];
__device__ float g_cand_v[2 * NB_TK * 8];
__device__ int   g_cand_i[2 * NB_TK * 8];
__device__ int   g_is64;
__device__ unsigned int g_done;

// ---------------- helpers ----------------
__device__ __forceinline__ float selu_f(float x) {
    const float sc = 1.0507009873554805f, al = 1.6732632423543772f;
    return x > 0.f ? sc * x : sc * al * expm1f(x);
}
__device__ __forceinline__ int clampn(int v) {
    return v < 0 ? 0 : (v >= NN ? NN - 1 : v);
}

// ---------------- kernels ----------------
// zero per-launch state; block 0 also detects int64-vs-int32 edge_index
__global__ void k_init(const int* __restrict__ ei32) {
    int i = blockIdx.x * 1024 + threadIdx.x;
    if (i < NN) { g_deg[i] = 0.f; g_cnt[i] = 0; }
    if (i == 0) g_done = 0u;
    if (blockIdx.x == 0) {
        __shared__ int any_nz;
        if (threadIdx.x == 0) any_nz = 0;
        __syncthreads();
        if (ei32[2 * threadIdx.x + 1] != 0) atomicOr(&any_nz, 1);
        __syncthreads();
        if (threadIdx.x == 0) g_is64 = any_nz ? 0 : 1;
    }
}

__global__ void k_prep(const void* __restrict__ eiv, const float* __restrict__ ew) {
    int e = blockIdx.x * blockDim.x + threadIdx.x;
    if (e >= NE) return;
    int s, d;
    if (g_is64) {
        const long long* ei = (const long long*)eiv;
        s = (int)ei[e]; d = (int)ei[NE + e];
    } else {
        const int* ei = (const int*)eiv;
        s = ei[e]; d = ei[NE + e];
    }
    s = clampn(s); d = clampn(d);
    g_sd[e] = make_int2(s, d);
    atomicAdd(&g_deg[d], ew[e]);
    atomicAdd(&g_cnt[d], 1);
}

// block-local exclusive scan of g_cnt
__global__ void k_scan1() {
    __shared__ int sm[1024];
    int t = threadIdx.x;
    int gid = blockIdx.x * 1024 + t;
    int x = (gid < NN) ? g_cnt[gid] : 0;
    sm[t] = x; __syncthreads();
    for (int off = 1; off < 1024; off <<= 1) {
        int v = (t >= off) ? sm[t - off] : 0;
        __syncthreads();
        sm[t] += v;
        __syncthreads();
    }
    if (gid < NN) g_pref[gid] = sm[t] - x;
    if (t == 1023) g_bsum[blockIdx.x] = sm[1023];
}

// add block offsets (serial 98-sum by t0) + rowstart/cur/dinv
__global__ void k_scan3(int nblk) {
    __shared__ int sb[128];
    __shared__ int soff;
    int t = threadIdx.x;
    if (t < 128) sb[t] = (t < nblk) ? g_bsum[t] : 0;
    __syncthreads();
    if (t == 0) {
        int s = 0;
        for (int j = 0; j < blockIdx.x; j++) s += sb[j];
        soff = s;
    }
    __syncthreads();
    int gid = blockIdx.x * 1024 + t;
    if (gid < NN) {
        int rs = g_pref[gid] + soff;
        g_rowstart[gid] = rs;
        g_cur[gid] = rs;
        g_dinv[gid] = rsqrtf(g_deg[gid] + 1.0f);
    }
    if (gid == 0) g_rowstart[NN] = NE;
}

// h = x @ W1
__global__ void k_mm1(const float* __restrict__ X, const float* __restrict__ W) {
    __shared__ float sW[INC * HID];
    for (int i = threadIdx.x; i < INC * HID; i += blockDim.x) sW[i] = W[i];
    __syncthreads();
    int n = blockIdx.x * blockDim.x + threadIdx.x;
    if (n >= NN) return;
    float acc[HID];
#pragma unroll
    for (int o = 0; o < HID; o++) acc[o] = 0.f;
    const float* xr = X + (long)n * INC;
#pragma unroll
    for (int k = 0; k < INC; k++) {
        float xv = __ldg(xr + k);
#pragma unroll
        for (int o = 0; o < HID; o++) acc[o] += xv * sW[k * HID + o];
    }
    float* yr = g_h + (long)n * HID;
#pragma unroll
    for (int o = 0; o < HID; o++) yr[o] = acc[o];
}

// build CSR entries (src, norm) packed 8B
__global__ void k_scatter(const float* __restrict__ ew) {
    int e = blockIdx.x * blockDim.x + threadIdx.x;
    if (e >= NE) return;
    int2 sd = g_sd[e];
    float w = g_dinv[sd.x] * ew[e] * g_dinv[sd.y];
    int pos = atomicAdd(&g_cur[sd.y], 1);
    unsigned long long ent = ((unsigned long long)__float_as_uint(w) << 32) |
                             (unsigned int)sd.x;
    g_csr[pos] = ent;
}

// CSR aggregation: warp per node. 30 active lanes = 3 edges x 10 chunks.
// software-pipelined csr entry prefetch; cross-group shfl reduce at end.
// agg[n] = sum_e w_e * h[src_e] + h[n]*dinv[n]^2 + b
__global__ void k_aggc(const float* __restrict__ b) {
    int warp = blockIdx.x * 8 + (threadIdx.x >> 5);
    if (warp >= NN) return;
    int lane = threadIdx.x & 31;
    int grp = lane / 10;          // 0..2 active, 3 idle (lanes 30,31)
    int chunk = lane - grp * 10;  // 0..9
    bool act = lane < 30;
    int beg = g_rowstart[warp], end = g_rowstart[warp + 1];
    const float4* h4 = reinterpret_cast<const float4*>(g_h);
    float4 acc = make_float4(0.f, 0.f, 0.f, 0.f);

    int ee = beg + grp;
    unsigned long long ent = (act && ee < end) ? __ldg(&g_csr[ee]) : 0ULL;
    for (int e = beg; e < end; e += 3) {
        bool curv = act && (e + grp) < end;
        unsigned long long cur = ent;
        int en = e + 3 + grp;
        ent = (act && en < end) ? __ldg(&g_csr[en]) : 0ULL;
        if (curv) {
            int s = (int)(unsigned int)cur;
            float w = __uint_as_float((unsigned int)(cur >> 32));
            float4 v = __ldg(h4 + s * 10 + chunk);
            acc.x += v.x * w; acc.y += v.y * w;
            acc.z += v.z * w; acc.w += v.w * w;
        }
    }
    // reduce grp1,grp2 into grp0
    float rx = acc.x + __shfl_down_sync(0xffffffffu, acc.x, 10)
                     + __shfl_down_sync(0xffffffffu, acc.x, 20);
    float ry = acc.y + __shfl_down_sync(0xffffffffu, acc.y, 10)
                     + __shfl_down_sync(0xffffffffu, acc.y, 20);
    float rz = acc.z + __shfl_down_sync(0xffffffffu, acc.z, 10)
                     + __shfl_down_sync(0xffffffffu, acc.z, 20);
    float rw = acc.w + __shfl_down_sync(0xffffffffu, acc.w, 10)
                     + __shfl_down_sync(0xffffffffu, acc.w, 20);
    if (lane < 10) {
        float di = g_dinv[warp], d2 = di * di;
        float4 hv = h4[warp * 10 + lane];
        float4 bv = __ldg(reinterpret_cast<const float4*>(b) + lane);
        float4 r;
        r.x = rx + hv.x * d2 + bv.x;
        r.y = ry + hv.y * d2 + bv.y;
        r.z = rz + hv.z * d2 + bv.z;
        r.w = rw + hv.w * d2 + bv.w;
        reinterpret_cast<float4*>(g_agg)[warp * 10 + lane] = r;
    }
}

// x1 = selu(ln(agg)); h2 = x1 @ W2 -> g_h (overwrite)
__global__ void k_post1mm(const float* __restrict__ lw, const float* __restrict__ lb,
                          const float* __restrict__ W2) {
    __shared__ float sW[HID * HID];
    for (int i = threadIdx.x; i < HID * HID; i += blockDim.x) sW[i] = W2[i];
    __syncthreads();
    int n = blockIdx.x * blockDim.x + threadIdx.x;
    if (n >= NN) return;
    float v[HID];
    const float4* ag = reinterpret_cast<const float4*>(g_agg) + n * (HID / 4);
    float s = 0.f;
#pragma unroll
    for (int j = 0; j < HID / 4; j++) {
        float4 a4 = ag[j];
        v[4 * j + 0] = a4.x; v[4 * j + 1] = a4.y;
        v[4 * j + 2] = a4.z; v[4 * j + 3] = a4.w;
        s += a4.x + a4.y + a4.z + a4.w;
    }
    float m = s * (1.f / HID);
    float vs = 0.f;
#pragma unroll
    for (int f = 0; f < HID; f++) { float dd = v[f] - m; vs += dd * dd; }
    float inv = rsqrtf(vs * (1.f / HID) + 1e-5f);
#pragma unroll
    for (int f = 0; f < HID; f++)
        v[f] = selu_f((v[f] - m) * inv * __ldg(lw + f) + __ldg(lb + f));
    float acc[HID];
#pragma unroll
    for (int o = 0; o < HID; o++) acc[o] = 0.f;
#pragma unroll
    for (int k = 0; k < HID; k++) {
        float xv = v[k];
#pragma unroll
        for (int o = 0; o < HID; o++) acc[o] += xv * sW[k * HID + o];
    }
    float* yr = g_h + (long)n * HID;
#pragma unroll
    for (int o = 0; o < HID; o++) yr[o] = acc[o];
}

// x2 = selu(ln(agg)); x3 = selu(x2@Wf+bf) -> g_x3 + outx3; a = attention score
__global__ void k_post2(const float* __restrict__ lw, const float* __restrict__ lb,
                        const float* __restrict__ Wf, const float* __restrict__ bf,
                        const float* __restrict__ Wt, const float* __restrict__ bt,
                        const float* __restrict__ Ws, const float* __restrict__ bs,
                        const float* __restrict__ Wc, const float* __restrict__ bc,
                        float* __restrict__ outx3) {
    __shared__ float sWf[HID * D1];
    __shared__ float sWt[D1 * D2];
    __shared__ float sWs[D1 * D2];
    __shared__ float sWc[D2];
    __shared__ float sbf[D1], sbt[D2], sbs[D2];
    int t = threadIdx.x;
    for (int i = t; i < HID * D1; i += blockDim.x) sWf[i] = Wf[i];
    for (int i = t; i < D1 * D2; i += blockDim.x) { sWt[i] = Wt[i]; sWs[i] = Ws[i]; }
    if (t < D2) { sWc[t] = Wc[t]; sbt[t] = bt[t]; sbs[t] = bs[t]; }
    if (t < D1) sbf[t] = bf[t];
    __syncthreads();
    int n = blockIdx.x * blockDim.x + t;
    if (n >= NN) return;
    float v[HID];
    const float4* ag = reinterpret_cast<const float4*>(g_agg) + n * (HID / 4);
    float s = 0.f;
#pragma unroll
    for (int j = 0; j < HID / 4; j++) {
        float4 a4 = ag[j];
        v[4 * j + 0] = a4.x; v[4 * j + 1] = a4.y;
        v[4 * j + 2] = a4.z; v[4 * j + 3] = a4.w;
        s += a4.x + a4.y + a4.z + a4.w;
    }
    float m = s * (1.f / HID);
    float vs = 0.f;
#pragma unroll
    for (int f = 0; f < HID; f++) { float dd = v[f] - m; vs += dd * dd; }
    float inv = rsqrtf(vs * (1.f / HID) + 1e-5f);
#pragma unroll
    for (int f = 0; f < HID; f++)
        v[f] = selu_f((v[f] - m) * inv * __ldg(lw + f) + __ldg(lb + f));
    float x3[D1];
#pragma unroll
    for (int o = 0; o < D1; o++) {
        float acc = sbf[o];
#pragma unroll
        for (int k = 0; k < HID; k++) acc += v[k] * sWf[k * D1 + o];
        x3[o] = selu_f(acc);
    }
    float* xo = g_x3 + (long)n * D1;
    float* xo2 = outx3 + (long)n * D1;
#pragma unroll
    for (int o = 0; o < D1; o++) { xo[o] = x3[o]; xo2[o] = x3[o]; }
    float a = __ldg(bc);
#pragma unroll
    for (int j = 0; j < D2; j++) {
        float zt = sbt[j], zs = sbs[j];
#pragma unroll
        for (int k = 0; k < D1; k++) { zt += x3[k] * sWt[k * D2 + j]; zs += x3[k] * sWs[k * D2 + j]; }
        a += tanhf(zt) * (1.f / (1.f + expf(-zs))) * sWc[j];
    }
    g_a[n] = a;
}

// per-block (m, s, p) partials; last block finalizes gmax/denom/pooled
__global__ void k_softpool() {
    __shared__ float sm[256];
    __shared__ float sbp[D1];
    __shared__ bool isLast;
    int t = threadIdx.x;
    float mx = __int_as_float(0xff800000);
    for (int i = blockIdx.x * 256 + t; i < NN; i += NB_SP * 256)
        mx = fmaxf(mx, g_a[i]);
    sm[t] = mx; __syncthreads();
    for (int st = 128; st > 0; st >>= 1) {
        if (t < st) sm[t] = fmaxf(sm[t], sm[t + st]);
        __syncthreads();
    }
    float mb = sm[0];
    __syncthreads();
    float ssum = 0.f;
    float acc[D1];
#pragma unroll
    for (int f = 0; f < D1; f++) acc[f] = 0.f;
    for (int i = blockIdx.x * 256 + t; i < NN; i += NB_SP * 256) {
        float w = expf(g_a[i] - mb);
        ssum += w;
        const float4* xr = reinterpret_cast<const float4*>(g_x3) + i * (D1 / 4);
#pragma unroll
        for (int j = 0; j < D1 / 4; j++) {
            float4 t4 = __ldg(xr + j);
            acc[4 * j + 0] += w * t4.x; acc[4 * j + 1] += w * t4.y;
            acc[4 * j + 2] += w * t4.z; acc[4 * j + 3] += w * t4.w;
        }
    }
    sm[t] = ssum; __syncthreads();
    for (int st = 128; st > 0; st >>= 1) {
        if (t < st) sm[t] += sm[t + st];
        __syncthreads();
    }
    if (t == 0) { g_bm[blockIdx.x] = mb; g_bs[blockIdx.x] = sm[0]; }
    if (t < D1) sbp[t] = 0.f;
    __syncthreads();
#pragma unroll
    for (int f = 0; f < D1; f++) {
        float vv = acc[f];
        for (int off = 16; off; off >>= 1) vv += __shfl_down_sync(0xffffffffu, vv, off);
        if ((t & 31) == 0) atomicAdd(&sbp[f], vv);
    }
    __syncthreads();
    if (t < D1) g_bp[blockIdx.x * D1 + t] = sbp[t];
    // last-block finalize
    __threadfence();
    if (t == 0) {
        unsigned int prev = atomicAdd(&g_done, 1u);
        isLast = (prev == NB_SP - 1);
    }
    __syncthreads();
    if (!isLast) return;
    __threadfence();
    float mt = (t < NB_SP) ? g_bm[t] : __int_as_float(0xff800000);
    sm[t] = mt; __syncthreads();
    for (int st = 128; st > 0; st >>= 1) {
        if (t < st) sm[t] = fmaxf(sm[t], sm[t + st]);
        __syncthreads();
    }
    float M = sm[0];
    __syncthreads();
    float scale = (t < NB_SP) ? expf(mt - M) : 0.f;
    sm[t] = (t < NB_SP) ? g_bs[t] * scale : 0.f;
    __syncthreads();
    for (int st = 128; st > 0; st >>= 1) {
        if (t < st) sm[t] += sm[t + st];
        __syncthreads();
    }
    float denom = sm[0];
    if (t == 0) { g_gmax = M; g_denom = denom; }
    __syncthreads();
    for (int f = 0; f < D1; f++) {
        sm[t] = (t < NB_SP) ? g_bp[t * D1 + f] * scale : 0.f;
        __syncthreads();
        for (int st = 128; st > 0; st >>= 1) {
            if (t < st) sm[t] += sm[t + st];
            __syncthreads();
        }
        if (t == 0) g_pooled[f] = sm[0] / denom;
        __syncthreads();
    }
}

// stage-1 topk: each block = 1024 contiguous elements; also writes softmax A
__global__ void k_topk1(float* __restrict__ outA) {
    __shared__ float sv[1024];
    __shared__ int si[1024];
    int t = threadIdx.x;
    int gid = blockIdx.x * 1024 + t;
    bool valid = gid < NN;
    float a = valid ? g_a[gid] : 0.f;
    if (valid) outA[gid] = expf(a - g_gmax) / g_denom;
    float vt = valid ? a : __int_as_float(0xff800000);
    float vb = valid ? a : __int_as_float(0x7f800000);
    int myi = valid ? gid : 0x7fffffff;
    for (int pass = 0; pass < 8; pass++) {
        sv[t] = vt; si[t] = myi; __syncthreads();
        for (int st = 512; st > 0; st >>= 1) {
            if (t < st) {
                float v2 = sv[t + st]; int i2 = si[t + st];
                if (v2 > sv[t] || (v2 == sv[t] && i2 < si[t])) { sv[t] = v2; si[t] = i2; }
            }
            __syncthreads();
        }
        if (t == 0) {
            g_cand_v[blockIdx.x * 8 + pass] = sv[0];
            g_cand_i[blockIdx.x * 8 + pass] = si[0];
        }
        if (myi == si[0]) vt = __int_as_float(0xff800000);
        __syncthreads();
    }
    for (int pass = 0; pass < 8; pass++) {
        sv[t] = vb; si[t] = myi; __syncthreads();
        for (int st = 512; st > 0; st >>= 1) {
            if (t < st) {
                float v2 = sv[t + st]; int i2 = si[t + st];
                if (v2 < sv[t] || (v2 == sv[t] && i2 < si[t])) { sv[t] = v2; si[t] = i2; }
            }
            __syncthreads();
        }
        if (t == 0) {
            g_cand_v[NB_TK * 8 + blockIdx.x * 8 + pass] = sv[0];
            g_cand_i[NB_TK * 8 + blockIdx.x * 8 + pass] = si[0];
        }
        if (myi == si[0]) vb = __int_as_float(0x7f800000);
        __syncthreads();
    }
}

// stage-2 merge + final tail math
__global__ void k_topk2(const float* __restrict__ Wcls, const float* __restrict__ bcls,
                        const float* __restrict__ Wcell, const float* __restrict__ bcell,
                        const int* __restrict__ labelp, float* __restrict__ out) {
    __shared__ float sv[1024];
    __shared__ int si[1024];
    __shared__ int ssel[16];
    int t = threadIdx.x;
    float vt = g_cand_v[t];
    int it = g_cand_i[t];
    for (int pass = 0; pass < 8; pass++) {
        sv[t] = vt; si[t] = it; __syncthreads();
        for (int st = 512; st > 0; st >>= 1) {
            if (t < st) {
                float v2 = sv[t + st]; int i2 = si[t + st];
                if (v2 > sv[t] || (v2 == sv[t] && i2 < si[t])) { sv[t] = v2; si[t] = i2; }
            }
            __syncthreads();
        }
        if (t == 0) ssel[pass] = si[0];
        if (it == si[0]) vt = __int_as_float(0xff800000);
        __syncthreads();
    }
    float vb = g_cand_v[NB_TK * 8 + t];
    int ib = g_cand_i[NB_TK * 8 + t];
    for (int pass = 0; pass < 8; pass++) {
        sv[t] = vb; si[t] = ib; __syncthreads();
        for (int st = 512; st > 0; st >>= 1) {
            if (t < st) {
                float v2 = sv[t + st]; int i2 = si[t + st];
                if (v2 < sv[t] || (v2 == sv[t] && i2 < si[t])) { sv[t] = v2; si[t] = i2; }
            }
            __syncthreads();
        }
        if (t == 0) ssel[8 + pass] = si[0];
        if (ib == si[0]) vb = __int_as_float(0x7f800000);
        __syncthreads();
    }
    if (t != 0) return;
    float logits[NCLS];
#pragma unroll
    for (int c = 0; c < NCLS; c++) {
        float s = bcls[c];
#pragma unroll
        for (int f = 0; f < D1; f++) s += g_pooled[f] * Wcls[f * NCLS + c];
        logits[c] = s;
    }
    float mx = fmaxf(logits[0], fmaxf(logits[1], logits[2]));
    float e0 = expf(logits[0] - mx), e1 = expf(logits[1] - mx), e2 = expf(logits[2] - mx);
    float es = e0 + e1 + e2;
    int yhat = 0;
    if (logits[1] > logits[yhat]) yhat = 1;
    if (logits[2] > logits[yhat]) yhat = 2;
    out[0] = logits[0]; out[1] = logits[1]; out[2] = logits[2];
    out[3] = e0 / es; out[4] = e1 / es; out[5] = e2 / es;
    out[6] = (float)yhat;
    int label = labelp[0];
    if (label < 0) label = 0;
    if (label >= NCLS) label = NCLS - 1;
    const float* Wl = Wcell + label * D1 * 2;
    const float* bl = bcell + label * 2;
    float loss = 0.f;
    for (int i = 0; i < 16; i++) {
        int node = ssel[i];
        if (node < 0 || node >= NN) node = 0;
        int tgt = (i < 8) ? 1 : 0;
        const float* xr = g_x3 + (long)node * D1;
        float l0 = bl[0], l1 = bl[1];
#pragma unroll
        for (int f = 0; f < D1; f++) { l0 += xr[f] * Wl[f * 2]; l1 += xr[f] * Wl[f * 2 + 1]; }
        float u0 = l0 + (tgt == 1 ? 1.f : 0.f);
        float u1 = l1 + (tgt == 0 ? 1.f : 0.f);
        float mm = fmaxf(u0, u1);
        float lse = mm + logf(expf(u0 - mm) + expf(u1 - mm));
        float sy = tgt ? l1 : l0;
        loss += lse - sy;
    }
    out[OUT_LOSS] = loss * (1.f / 16.f);
}

// ---------------- launch ----------------
extern "C" void kernel_launch(void* const* d_in, const int* in_sizes, int n_in,
                              void* d_out, int out_size) {
    const float* x = (const float*)d_in[0];
    const void* ei = d_in[1];
    const float* ew = (const float*)d_in[2];
    const int* label = (const int*)d_in[3];
    const float* W1 = (const float*)d_in[4];
    const float* b1 = (const float*)d_in[5];
    const float* ln1w = (const float*)d_in[6];
    const float* ln1b = (const float*)d_in[7];
    const float* W2 = (const float*)d_in[8];
    const float* b2 = (const float*)d_in[9];
    const float* ln2w = (const float*)d_in[10];
    const float* ln2b = (const float*)d_in[11];
    const float* Wf = (const float*)d_in[12];
    const float* bf = (const float*)d_in[13];
    const float* Wt = (const float*)d_in[14];
    const float* bt = (const float*)d_in[15];
    const float* Ws = (const float*)d_in[16];
    const float* bs = (const float*)d_in[17];
    const float* Wc = (const float*)d_in[18];
    const float* bc = (const float*)d_in[19];
    const float* Wcls = (const float*)d_in[20];
    const float* bcls = (const float*)d_in[21];
    const float* Wcell = (const float*)d_in[22];
    const float* bcell = (const float*)d_in[23];
    float* out = (float*)d_out;

    int nb_scan = (NN + 1023) / 1024;        // 98
    int nb_edge = (NE + 255) / 256;          // 7813
    int nb_node = (NN + 127) / 128;          // 782
    int nb_aggc = (NN + 7) / 8;              // 12500

    k_init<<<nb_scan, 1024>>>((const int*)ei);
    k_prep<<<nb_edge, 256>>>(ei, ew);
    k_scan1<<<nb_scan, 1024>>>();
    k_scan3<<<nb_scan, 1024>>>(nb_scan);
    k_mm1<<<nb_node, 128>>>(x, W1);
    k_scatter<<<nb_edge, 256>>>(ew);

    // layer 1
    k_aggc<<<nb_aggc, 256>>>(b1);
    k_post1mm<<<nb_node, 128>>>(ln1w, ln1b, W2);
    // layer 2
    k_aggc<<<nb_aggc, 256>>>(b2);
    k_post2<<<nb_node, 128>>>(ln2w, ln2b, Wf, bf, Wt, bt, Ws, bs, Wc, bc,
                              out + OUT_X3);

    // softmax + pool (fused finalize)
    k_softpool<<<NB_SP, 256>>>();

    // topk (+A write) and tail (+final)
    k_topk1<<<NB_TK, 1024>>>(out + OUT_A);
    k_topk2<<<1, 1024>>>(Wcls, bcls, Wcell, bcell, label, out);
}

// round 6
// speedup vs baseline: 3.3613x; 1.0061x over previous
#include <cuda_runtime.h>
#include <cuda_fp16.h>
#include <math.h>

#define NN 100000
#define NE 2000000
#define INC 30
#define HID 40
#define D1 20
#define D2 10
#define NCLS 3
#define NB_SP 128   // softpool blocks
#define NB_TK 128   // topk stage-1 blocks

// out layout: logits[3], Y_prob[3], Y_hat[1], A[NN], x3[NN*D1], cell_loss[1]
#define OUT_A 7
#define OUT_X3 (7 + NN)
#define OUT_LOSS (7 + NN + NN * D1)

// ---------------- scratch ----------------
__device__ __align__(16) __half g_h16[NN * HID];   // fp16 features for gather
__device__ __align__(16) float g_agg[NN * HID];
__device__ __align__(16) float g_x3[NN * D1];
__device__ float g_a[NN];
__device__ float g_deg[NN];
__device__ float g_dinv[NN];
__device__ int   g_cnt[NN];
__device__ int   g_pref[NN];
__device__ int   g_bsum[128];
__device__ int   g_rowstart[NN + 1];
__device__ int   g_cur[NN];
__device__ int2  g_sd[NE];
__device__ unsigned long long g_csr[NE];
__device__ float g_bm[NB_SP];
__device__ float g_bs[NB_SP];
__device__ float g_bp[NB_SP * D1];
__device__ float g_gmax;
__device__ float g_denom;
__device__ float g_pooled[D1];
__device__ float g_cand_v[2 * NB_TK * 8];
__device__ int   g_cand_i[2 * NB_TK * 8];
__device__ int   g_is64;
__device__ unsigned int g_done;

// ---------------- helpers ----------------
__device__ __forceinline__ float selu_f(float x) {
    const float sc = 1.0507009873554805f, al = 1.6732632423543772f;
    return x > 0.f ? sc * x : sc * al * expm1f(x);
}
__device__ __forceinline__ int clampn(int v) {
    return v < 0 ? 0 : (v >= NN ? NN - 1 : v);
}

// write 40 fp32 values as fp16 row (5 uint4 stores)
__device__ __forceinline__ void store_h16_row(int n, const float* v) {
    uint4* dst = reinterpret_cast<uint4*>(g_h16) + n * 5;
#pragma unroll
    for (int c = 0; c < 5; c++) {
        __half2 p0 = __floats2half2_rn(v[c * 8 + 0], v[c * 8 + 1]);
        __half2 p1 = __floats2half2_rn(v[c * 8 + 2], v[c * 8 + 3]);
        __half2 p2 = __floats2half2_rn(v[c * 8 + 4], v[c * 8 + 5]);
        __half2 p3 = __floats2half2_rn(v[c * 8 + 6], v[c * 8 + 7]);
        uint4 u;
        u.x = *reinterpret_cast<unsigned int*>(&p0);
        u.y = *reinterpret_cast<unsigned int*>(&p1);
        u.z = *reinterpret_cast<unsigned int*>(&p2);
        u.w = *reinterpret_cast<unsigned int*>(&p3);
        dst[c] = u;
    }
}

__device__ __forceinline__ void unpack8(uint4 u, float* f) {
    __half2 p0 = *reinterpret_cast<__half2*>(&u.x);
    __half2 p1 = *reinterpret_cast<__half2*>(&u.y);
    __half2 p2 = *reinterpret_cast<__half2*>(&u.z);
    __half2 p3 = *reinterpret_cast<__half2*>(&u.w);
    float2 f0 = __half22float2(p0), f1 = __half22float2(p1);
    float2 f2 = __half22float2(p2), f3 = __half22float2(p3);
    f[0] = f0.x; f[1] = f0.y; f[2] = f1.x; f[3] = f1.y;
    f[4] = f2.x; f[5] = f2.y; f[6] = f3.x; f[7] = f3.y;
}

// ---------------- kernels ----------------
// zero per-launch state; block 0 also detects int64-vs-int32 edge_index
__global__ void k_init(const int* __restrict__ ei32) {
    int i = blockIdx.x * 1024 + threadIdx.x;
    if (i < NN) { g_deg[i] = 0.f; g_cnt[i] = 0; }
    if (i == 0) g_done = 0u;
    if (blockIdx.x == 0) {
        __shared__ int any_nz;
        if (threadIdx.x == 0) any_nz = 0;
        __syncthreads();
        if (ei32[2 * threadIdx.x + 1] != 0) atomicOr(&any_nz, 1);
        __syncthreads();
        if (threadIdx.x == 0) g_is64 = any_nz ? 0 : 1;
    }
}

__global__ void k_prep(const void* __restrict__ eiv, const float* __restrict__ ew) {
    int e = blockIdx.x * blockDim.x + threadIdx.x;
    if (e >= NE) return;
    int s, d;
    if (g_is64) {
        const long long* ei = (const long long*)eiv;
        s = (int)ei[e]; d = (int)ei[NE + e];
    } else {
        const int* ei = (const int*)eiv;
        s = ei[e]; d = ei[NE + e];
    }
    s = clampn(s); d = clampn(d);
    g_sd[e] = make_int2(s, d);
    atomicAdd(&g_deg[d], ew[e]);
    atomicAdd(&g_cnt[d], 1);
}

// block-local exclusive scan of g_cnt
__global__ void k_scan1() {
    __shared__ int sm[1024];
    int t = threadIdx.x;
    int gid = blockIdx.x * 1024 + t;
    int x = (gid < NN) ? g_cnt[gid] : 0;
    sm[t] = x; __syncthreads();
    for (int off = 1; off < 1024; off <<= 1) {
        int v = (t >= off) ? sm[t - off] : 0;
        __syncthreads();
        sm[t] += v;
        __syncthreads();
    }
    if (gid < NN) g_pref[gid] = sm[t] - x;
    if (t == 1023) g_bsum[blockIdx.x] = sm[1023];
}

// add block offsets (serial 98-sum by t0) + rowstart/cur/dinv
__global__ void k_scan3(int nblk) {
    __shared__ int sb[128];
    __shared__ int soff;
    int t = threadIdx.x;
    if (t < 128) sb[t] = (t < nblk) ? g_bsum[t] : 0;
    __syncthreads();
    if (t == 0) {
        int s = 0;
        for (int j = 0; j < blockIdx.x; j++) s += sb[j];
        soff = s;
    }
    __syncthreads();
    int gid = blockIdx.x * 1024 + t;
    if (gid < NN) {
        int rs = g_pref[gid] + soff;
        g_rowstart[gid] = rs;
        g_cur[gid] = rs;
        g_dinv[gid] = rsqrtf(g_deg[gid] + 1.0f);
    }
    if (gid == 0) g_rowstart[NN] = NE;
}

// h = x @ W1 -> fp16
__global__ void k_mm1(const float* __restrict__ X, const float* __restrict__ W) {
    __shared__ float sW[INC * HID];
    for (int i = threadIdx.x; i < INC * HID; i += blockDim.x) sW[i] = W[i];
    __syncthreads();
    int n = blockIdx.x * blockDim.x + threadIdx.x;
    if (n >= NN) return;
    float acc[HID];
#pragma unroll
    for (int o = 0; o < HID; o++) acc[o] = 0.f;
    const float* xr = X + (long)n * INC;
#pragma unroll
    for (int k = 0; k < INC; k++) {
        float xv = __ldg(xr + k);
#pragma unroll
        for (int o = 0; o < HID; o++) acc[o] += xv * sW[k * HID + o];
    }
    store_h16_row(n, acc);
}

// build CSR entries (src, norm) packed 8B
__global__ void k_scatter(const float* __restrict__ ew) {
    int e = blockIdx.x * blockDim.x + threadIdx.x;
    if (e >= NE) return;
    int2 sd = g_sd[e];
    float w = g_dinv[sd.x] * ew[e] * g_dinv[sd.y];
    int pos = atomicAdd(&g_cur[sd.y], 1);
    unsigned long long ent = ((unsigned long long)__float_as_uint(w) << 32) |
                             (unsigned int)sd.x;
    g_csr[pos] = ent;
}

// CSR aggregation (fp16 gather): warp per node, 30 lanes = 6 edges x 5 chunks.
// agg[n] = sum_e w_e * h[src_e] + h[n]*dinv[n]^2 + b   (fp32 accumulate)
__global__ void k_aggc(const float* __restrict__ b) {
    int warp = blockIdx.x * 8 + (threadIdx.x >> 5);
    if (warp >= NN) return;
    int lane = threadIdx.x & 31;
    int grp = lane / 5;           // 0..5 active; lanes 30,31 idle
    int chunk = lane - grp * 5;   // 0..4
    bool act = lane < 30;
    int beg = g_rowstart[warp], end = g_rowstart[warp + 1];
    const uint4* h4 = reinterpret_cast<const uint4*>(g_h16);
    float acc[8];
#pragma unroll
    for (int k = 0; k < 8; k++) acc[k] = 0.f;

    int ee = beg + grp;
    unsigned long long ent = (act && ee < end) ? __ldg(&g_csr[ee]) : 0ULL;
    for (int e = beg; e < end; e += 6) {
        bool curv = act && (e + grp) < end;
        unsigned long long cur = ent;
        int en = e + 6 + grp;
        ent = (act && en < end) ? __ldg(&g_csr[en]) : 0ULL;
        if (curv) {
            int s = (int)(unsigned int)cur;
            float w = __uint_as_float((unsigned int)(cur >> 32));
            uint4 u = __ldg(h4 + s * 5 + chunk);
            float f[8];
            unpack8(u, f);
#pragma unroll
            for (int k = 0; k < 8; k++) acc[k] += f[k] * w;
        }
    }
    // reduce 6 groups (spaced 5) into lanes 0-4:
    // step1 off15 -> pairs in lanes 0-14; zero lanes>=15; then off5, off10.
#pragma unroll
    for (int k = 0; k < 8; k++) {
        float v = acc[k];
        v += __shfl_down_sync(0xffffffffu, v, 15);
        if (lane >= 15) v = 0.f;
        v += __shfl_down_sync(0xffffffffu, v, 5);
        v += __shfl_down_sync(0xffffffffu, v, 10);
        acc[k] = v;
    }
    if (lane < 5) {
        float di = g_dinv[warp], d2 = di * di;
        uint4 u = h4[warp * 5 + lane];
        float hf[8];
        unpack8(u, hf);
        const float4* b4 = reinterpret_cast<const float4*>(b);
        float4 b0 = __ldg(b4 + lane * 2);
        float4 b1 = __ldg(b4 + lane * 2 + 1);
        float4 r0, r1;
        r0.x = acc[0] + hf[0] * d2 + b0.x;
        r0.y = acc[1] + hf[1] * d2 + b0.y;
        r0.z = acc[2] + hf[2] * d2 + b0.z;
        r0.w = acc[3] + hf[3] * d2 + b0.w;
        r1.x = acc[4] + hf[4] * d2 + b1.x;
        r1.y = acc[5] + hf[5] * d2 + b1.y;
        r1.z = acc[6] + hf[6] * d2 + b1.z;
        r1.w = acc[7] + hf[7] * d2 + b1.w;
        float4* ag4 = reinterpret_cast<float4*>(g_agg) + warp * 10 + lane * 2;
        ag4[0] = r0;
        ag4[1] = r1;
    }
}

// x1 = selu(ln(agg)); h2 = x1 @ W2 -> g_h16 (overwrite)
__global__ void k_post1mm(const float* __restrict__ lw, const float* __restrict__ lb,
                          const float* __restrict__ W2) {
    __shared__ float sW[HID * HID];
    for (int i = threadIdx.x; i < HID * HID; i += blockDim.x) sW[i] = W2[i];
    __syncthreads();
    int n = blockIdx.x * blockDim.x + threadIdx.x;
    if (n >= NN) return;
    float v[HID];
    const float4* ag = reinterpret_cast<const float4*>(g_agg) + n * (HID / 4);
    float s = 0.f;
#pragma unroll
    for (int j = 0; j < HID / 4; j++) {
        float4 a4 = ag[j];
        v[4 * j + 0] = a4.x; v[4 * j + 1] = a4.y;
        v[4 * j + 2] = a4.z; v[4 * j + 3] = a4.w;
        s += a4.x + a4.y + a4.z + a4.w;
    }
    float m = s * (1.f / HID);
    float vs = 0.f;
#pragma unroll
    for (int f = 0; f < HID; f++) { float dd = v[f] - m; vs += dd * dd; }
    float inv = rsqrtf(vs * (1.f / HID) + 1e-5f);
#pragma unroll
    for (int f = 0; f < HID; f++)
        v[f] = selu_f((v[f] - m) * inv * __ldg(lw + f) + __ldg(lb + f));
    float acc[HID];
#pragma unroll
    for (int o = 0; o < HID; o++) acc[o] = 0.f;
#pragma unroll
    for (int k = 0; k < HID; k++) {
        float xv = v[k];
#pragma unroll
        for (int o = 0; o < HID; o++) acc[o] += xv * sW[k * HID + o];
    }
    store_h16_row(n, acc);
}

// x2 = selu(ln(agg)); x3 = selu(x2@Wf+bf) -> g_x3 + outx3; a = attention score
__global__ void k_post2(const float* __restrict__ lw, const float* __restrict__ lb,
                        const float* __restrict__ Wf, const float* __restrict__ bf,
                        const float* __restrict__ Wt, const float* __restrict__ bt,
                        const float* __restrict__ Ws, const float* __restrict__ bs,
                        const float* __restrict__ Wc, const float* __restrict__ bc,
                        float* __restrict__ outx3) {
    __shared__ float sWf[HID * D1];
    __shared__ float sWt[D1 * D2];
    __shared__ float sWs[D1 * D2];
    __shared__ float sWc[D2];
    __shared__ float sbf[D1], sbt[D2], sbs[D2];
    int t = threadIdx.x;
    for (int i = t; i < HID * D1; i += blockDim.x) sWf[i] = Wf[i];
    for (int i = t; i < D1 * D2; i += blockDim.x) { sWt[i] = Wt[i]; sWs[i] = Ws[i]; }
    if (t < D2) { sWc[t] = Wc[t]; sbt[t] = bt[t]; sbs[t] = bs[t]; }
    if (t < D1) sbf[t] = bf[t];
    __syncthreads();
    int n = blockIdx.x * blockDim.x + t;
    if (n >= NN) return;
    float v[HID];
    const float4* ag = reinterpret_cast<const float4*>(g_agg) + n * (HID / 4);
    float s = 0.f;
#pragma unroll
    for (int j = 0; j < HID / 4; j++) {
        float4 a4 = ag[j];
        v[4 * j + 0] = a4.x; v[4 * j + 1] = a4.y;
        v[4 * j + 2] = a4.z; v[4 * j + 3] = a4.w;
        s += a4.x + a4.y + a4.z + a4.w;
    }
    float m = s * (1.f / HID);
    float vs = 0.f;
#pragma unroll
    for (int f = 0; f < HID; f++) { float dd = v[f] - m; vs += dd * dd; }
    float inv = rsqrtf(vs * (1.f / HID) + 1e-5f);
#pragma unroll
    for (int f = 0; f < HID; f++)
        v[f] = selu_f((v[f] - m) * inv * __ldg(lw + f) + __ldg(lb + f));
    float x3[D1];
#pragma unroll
    for (int o = 0; o < D1; o++) {
        float acc = sbf[o];
#pragma unroll
        for (int k = 0; k < HID; k++) acc += v[k] * sWf[k * D1 + o];
        x3[o] = selu_f(acc);
    }
    float* xo = g_x3 + (long)n * D1;
    float* xo2 = outx3 + (long)n * D1;
#pragma unroll
    for (int o = 0; o < D1; o++) { xo[o] = x3[o]; xo2[o] = x3[o]; }
    float a = __ldg(bc);
#pragma unroll
    for (int j = 0; j < D2; j++) {
        float zt = sbt[j], zs = sbs[j];
#pragma unroll
        for (int k = 0; k < D1; k++) { zt += x3[k] * sWt[k * D2 + j]; zs += x3[k] * sWs[k * D2 + j]; }
        a += tanhf(zt) * (1.f / (1.f + expf(-zs))) * sWc[j];
    }
    g_a[n] = a;
}

// per-block (m, s, p) partials; last block finalizes gmax/denom/pooled
__global__ void k_softpool() {
    __shared__ float sm[256];
    __shared__ float sbp[D1];
    __shared__ bool isLast;
    int t = threadIdx.x;
    float mx = __int_as_float(0xff800000);
    for (int i = blockIdx.x * 256 + t; i < NN; i += NB_SP * 256)
        mx = fmaxf(mx, g_a[i]);
    sm[t] = mx; __syncthreads();
    for (int st = 128; st > 0; st >>= 1) {
        if (t < st) sm[t] = fmaxf(sm[t], sm[t + st]);
        __syncthreads();
    }
    float mb = sm[0];
    __syncthreads();
    float ssum = 0.f;
    float acc[D1];
#pragma unroll
    for (int f = 0; f < D1; f++) acc[f] = 0.f;
    for (int i = blockIdx.x * 256 + t; i < NN; i += NB_SP * 256) {
        float w = expf(g_a[i] - mb);
        ssum += w;
        const float4* xr = reinterpret_cast<const float4*>(g_x3) + i * (D1 / 4);
#pragma unroll
        for (int j = 0; j < D1 / 4; j++) {
            float4 t4 = __ldg(xr + j);
            acc[4 * j + 0] += w * t4.x; acc[4 * j + 1] += w * t4.y;
            acc[4 * j + 2] += w * t4.z; acc[4 * j + 3] += w * t4.w;
        }
    }
    sm[t] = ssum; __syncthreads();
    for (int st = 128; st > 0; st >>= 1) {
        if (t < st) sm[t] += sm[t + st];
        __syncthreads();
    }
    if (t == 0) { g_bm[blockIdx.x] = mb; g_bs[blockIdx.x] = sm[0]; }
    if (t < D1) sbp[t] = 0.f;
    __syncthreads();
#pragma unroll
    for (int f = 0; f < D1; f++) {
        float vv = acc[f];
        for (int off = 16; off; off >>= 1) vv += __shfl_down_sync(0xffffffffu, vv, off);
        if ((t & 31) == 0) atomicAdd(&sbp[f], vv);
    }
    __syncthreads();
    if (t < D1) g_bp[blockIdx.x * D1 + t] = sbp[t];
    // last-block finalize
    __threadfence();
    if (t == 0) {
        unsigned int prev = atomicAdd(&g_done, 1u);
        isLast = (prev == NB_SP - 1);
    }
    __syncthreads();
    if (!isLast) return;
    __threadfence();
    float mt = (t < NB_SP) ? g_bm[t] : __int_as_float(0xff800000);
    sm[t] = mt; __syncthreads();
    for (int st = 128; st > 0; st >>= 1) {
        if (t < st) sm[t] = fmaxf(sm[t], sm[t + st]);
        __syncthreads();
    }
    float M = sm[0];
    __syncthreads();
    float scale = (t < NB_SP) ? expf(mt - M) : 0.f;
    sm[t] = (t < NB_SP) ? g_bs[t] * scale : 0.f;
    __syncthreads();
    for (int st = 128; st > 0; st >>= 1) {
        if (t < st) sm[t] += sm[t + st];
        __syncthreads();
    }
    float denom = sm[0];
    if (t == 0) { g_gmax = M; g_denom = denom; }
    __syncthreads();
    for (int f = 0; f < D1; f++) {
        sm[t] = (t < NB_SP) ? g_bp[t * D1 + f] * scale : 0.f;
        __syncthreads();
        for (int st = 128; st > 0; st >>= 1) {
            if (t < st) sm[t] += sm[t + st];
            __syncthreads();
        }
        if (t == 0) g_pooled[f] = sm[0] / denom;
        __syncthreads();
    }
}

// stage-1 topk: each block = 1024 contiguous elements; also writes softmax A
__global__ void k_topk1(float* __restrict__ outA) {
    __shared__ float sv[1024];
    __shared__ int si[1024];
    int t = threadIdx.x;
    int gid = blockIdx.x * 1024 + t;
    bool valid = gid < NN;
    float a = valid ? g_a[gid] : 0.f;
    if (valid) outA[gid] = expf(a - g_gmax) / g_denom;
    float vt = valid ? a : __int_as_float(0xff800000);
    float vb = valid ? a : __int_as_float(0x7f800000);
    int myi = valid ? gid : 0x7fffffff;
    for (int pass = 0; pass < 8; pass++) {
        sv[t] = vt; si[t] = myi; __syncthreads();
        for (int st = 512; st > 0; st >>= 1) {
            if (t < st) {
                float v2 = sv[t + st]; int i2 = si[t + st];
                if (v2 > sv[t] || (v2 == sv[t] && i2 < si[t])) { sv[t] = v2; si[t] = i2; }
            }
            __syncthreads();
        }
        if (t == 0) {
            g_cand_v[blockIdx.x * 8 + pass] = sv[0];
            g_cand_i[blockIdx.x * 8 + pass] = si[0];
        }
        if (myi == si[0]) vt = __int_as_float(0xff800000);
        __syncthreads();
    }
    for (int pass = 0; pass < 8; pass++) {
        sv[t] = vb; si[t] = myi; __syncthreads();
        for (int st = 512; st > 0; st >>= 1) {
            if (t < st) {
                float v2 = sv[t + st]; int i2 = si[t + st];
                if (v2 < sv[t] || (v2 == sv[t] && i2 < si[t])) { sv[t] = v2; si[t] = i2; }
            }
            __syncthreads();
        }
        if (t == 0) {
            g_cand_v[NB_TK * 8 + blockIdx.x * 8 + pass] = sv[0];
            g_cand_i[NB_TK * 8 + blockIdx.x * 8 + pass] = si[0];
        }
        if (myi == si[0]) vb = __int_as_float(0x7f800000);
        __syncthreads();
    }
}

// stage-2 merge + final tail math
__global__ void k_topk2(const float* __restrict__ Wcls, const float* __restrict__ bcls,
                        const float* __restrict__ Wcell, const float* __restrict__ bcell,
                        const int* __restrict__ labelp, float* __restrict__ out) {
    __shared__ float sv[1024];
    __shared__ int si[1024];
    __shared__ int ssel[16];
    int t = threadIdx.x;
    float vt = g_cand_v[t];
    int it = g_cand_i[t];
    for (int pass = 0; pass < 8; pass++) {
        sv[t] = vt; si[t] = it; __syncthreads();
        for (int st = 512; st > 0; st >>= 1) {
            if (t < st) {
                float v2 = sv[t + st]; int i2 = si[t + st];
                if (v2 > sv[t] || (v2 == sv[t] && i2 < si[t])) { sv[t] = v2; si[t] = i2; }
            }
            __syncthreads();
        }
        if (t == 0) ssel[pass] = si[0];
        if (it == si[0]) vt = __int_as_float(0xff800000);
        __syncthreads();
    }
    float vb = g_cand_v[NB_TK * 8 + t];
    int ib = g_cand_i[NB_TK * 8 + t];
    for (int pass = 0; pass < 8; pass++) {
        sv[t] = vb; si[t] = ib; __syncthreads();
        for (int st = 512; st > 0; st >>= 1) {
            if (t < st) {
                float v2 = sv[t + st]; int i2 = si[t + st];
                if (v2 < sv[t] || (v2 == sv[t] && i2 < si[t])) { sv[t] = v2; si[t] = i2; }
            }
            __syncthreads();
        }
        if (t == 0) ssel[8 + pass] = si[0];
        if (ib == si[0]) vb = __int_as_float(0x7f800000);
        __syncthreads();
    }
    if (t != 0) return;
    float logits[NCLS];
#pragma unroll
    for (int c = 0; c < NCLS; c++) {
        float s = bcls[c];
#pragma unroll
        for (int f = 0; f < D1; f++) s += g_pooled[f] * Wcls[f * NCLS + c];
        logits[c] = s;
    }
    float mx = fmaxf(logits[0], fmaxf(logits[1], logits[2]));
    float e0 = expf(logits[0] - mx), e1 = expf(logits[1] - mx), e2 = expf(logits[2] - mx);
    float es = e0 + e1 + e2;
    int yhat = 0;
    if (logits[1] > logits[yhat]) yhat = 1;
    if (logits[2] > logits[yhat]) yhat = 2;
    out[0] = logits[0]; out[1] = logits[1]; out[2] = logits[2];
    out[3] = e0 / es; out[4] = e1 / es; out[5] = e2 / es;
    out[6] = (float)yhat;
    int label = labelp[0];
    if (label < 0) label = 0;
    if (label >= NCLS) label = NCLS - 1;
    const float* Wl = Wcell + label * D1 * 2;
    const float* bl = bcell + label * 2;
    float loss = 0.f;
    for (int i = 0; i < 16; i++) {
        int node = ssel[i];
        if (node < 0 || node >= NN) node = 0;
        int tgt = (i < 8) ? 1 : 0;
        const float* xr = g_x3 + (long)node * D1;
        float l0 = bl[0], l1 = bl[1];
#pragma unroll
        for (int f = 0; f < D1; f++) { l0 += xr[f] * Wl[f * 2]; l1 += xr[f] * Wl[f * 2 + 1]; }
        float u0 = l0 + (tgt == 1 ? 1.f : 0.f);
        float u1 = l1 + (tgt == 0 ? 1.f : 0.f);
        float mm = fmaxf(u0, u1);
        float lse = mm + logf(expf(u0 - mm) + expf(u1 - mm));
        float sy = tgt ? l1 : l0;
        loss += lse - sy;
    }
    out[OUT_LOSS] = loss * (1.f / 16.f);
}

// ---------------- launch ----------------
extern "C" void kernel_launch(void* const* d_in, const int* in_sizes, int n_in,
                              void* d_out, int out_size) {
    const float* x = (const float*)d_in[0];
    const void* ei = d_in[1];
    const float* ew = (const float*)d_in[2];
    const int* label = (const int*)d_in[3];
    const float* W1 = (const float*)d_in[4];
    const float* b1 = (const float*)d_in[5];
    const float* ln1w = (const float*)d_in[6];
    const float* ln1b = (const float*)d_in[7];
    const float* W2 = (const float*)d_in[8];
    const float* b2 = (const float*)d_in[9];
    const float* ln2w = (const float*)d_in[10];
    const float* ln2b = (const float*)d_in[11];
    const float* Wf = (const float*)d_in[12];
    const float* bf = (const float*)d_in[13];
    const float* Wt = (const float*)d_in[14];
    const float* bt = (const float*)d_in[15];
    const float* Ws = (const float*)d_in[16];
    const float* bs = (const float*)d_in[17];
    const float* Wc = (const float*)d_in[18];
    const float* bc = (const float*)d_in[19];
    const float* Wcls = (const float*)d_in[20];
    const float* bcls = (const float*)d_in[21];
    const float* Wcell = (const float*)d_in[22];
    const float* bcell = (const float*)d_in[23];
    float* out = (float*)d_out;

    int nb_scan = (NN + 1023) / 1024;        // 98
    int nb_edge = (NE + 255) / 256;          // 7813
    int nb_node = (NN + 127) / 128;          // 782
    int nb_aggc = (NN + 7) / 8;              // 12500

    k_init<<<nb_scan, 1024>>>((const int*)ei);
    k_prep<<<nb_edge, 256>>>(ei, ew);
    k_scan1<<<nb_scan, 1024>>>();
    k_scan3<<<nb_scan, 1024>>>(nb_scan);
    k_mm1<<<nb_node, 128>>>(x, W1);
    k_scatter<<<nb_edge, 256>>>(ew);

    // layer 1
    k_aggc<<<nb_aggc, 256>>>(b1);
    k_post1mm<<<nb_node, 128>>>(ln1w, ln1b, W2);
    // layer 2
    k_aggc<<<nb_aggc, 256>>>(b2);
    k_post2<<<nb_node, 128>>>(ln2w, ln2b, Wf, bf, Wt, bt, Ws, bs, Wc, bc,
                              out + OUT_X3);

    // softmax + pool (fused finalize)
    k_softpool<<<NB_SP, 256>>>();

    // topk (+A write) and tail (+final)
    k_topk1<<<NB_TK, 1024>>>(out + OUT_A);
    k_topk2<<<1, 1024>>>(Wcls, bcls, Wcell, bcell, label, out);
}